// round 14
// baseline (speedup 1.0000x reference)
#include <cuda_runtime.h>
#include <cstdint>

// Problem constants (fixed by setup_inputs)
#define B_      16
#define T_      1024
#define D_      384
#define MAXDUR_ 4
#define OUTLEN_ (T_ * MAXDUR_)      // 4096
#define D4_     (D_ / 4)            // 96 float4 per row

#define G_THREADS    384            // gather CTA size
#define ROWS_PER_CTA 16             // 16 rows * 96 f4 = 1536 f4 = 24KB
#define RPT          4              // rows per thread
#define TILE_BYTES   (ROWS_PER_CTA * D4_ * 16)   // 24576

// Scratch: per-output-frame source index, -1 => pad (zero fill)
__device__ int g_idx[B_ * OUTLEN_];

// ---------------------------------------------------------------------------
// Kernel 1: warp-shuffle inclusive scan + index scatter (R2 version verbatim —
// the proven-best scan; R13's slimmer variant measured slower).
// ---------------------------------------------------------------------------
__global__ void __launch_bounds__(T_) scan_idx_kernel(const int* __restrict__ ds) {
    __shared__ int wsum[32];
    const int b    = blockIdx.x;
    const int tid  = threadIdx.x;
    const int lane = tid & 31;
    const int warp = tid >> 5;

    const int d = ds[b * T_ + tid];

    int x = d;
    #pragma unroll
    for (int off = 1; off < 32; off <<= 1) {
        int y = __shfl_up_sync(0xffffffffu, x, off);
        if (lane >= off) x += y;
    }
    if (lane == 31) wsum[warp] = x;
    __syncthreads();

    if (warp == 0) {
        int w = wsum[lane];
        #pragma unroll
        for (int off = 1; off < 32; off <<= 1) {
            int y = __shfl_up_sync(0xffffffffu, w, off);
            if (lane >= off) w += y;
        }
        wsum[lane] = w;
    }
    __syncthreads();

    const int base  = (warp > 0) ? wsum[warp - 1] : 0;
    const int end   = base + x;
    const int start = end - d;
    const int total = wsum[31];

    int* __restrict__ gi = &g_idx[b * OUTLEN_];

    for (int t = start; t < end; t++) gi[t] = tid;
    for (int t = total + tid; t < OUTLEN_; t += T_) gi[t] = -1;
}

// ---------------------------------------------------------------------------
// Kernel 2: gather -> smem tile -> ONE bulk async store per CTA.
// Kills the STG.128 issue cost (12 cyc/instr/SMSP, ~32K cyc = the measured
// wall). Each CTA's 16 output rows are contiguous (24KB) in gmem, so a single
// cp.async.bulk.global.shared::cta covers them.
// ---------------------------------------------------------------------------
__global__ void __launch_bounds__(G_THREADS) gather_kernel(
    const float4* __restrict__ xs, float4* __restrict__ out) {
    __shared__ __align__(128) float4 tile[ROWS_PER_CTA * D4_];   // 24KB

    const int lr   = threadIdx.x / D4_;        // 0..3 local row within slice
    const int c    = threadIdx.x - lr * D4_;   // 0..95 column
    const int row0 = blockIdx.x * ROWS_PER_CTA;
    const int b    = row0 >> 12;               // same batch for whole CTA
    const float4* __restrict__ xb = xs + (size_t)b * T_ * D4_;

    // batch the 4 independent idx loads
    int idxs[RPT];
    #pragma unroll
    for (int k = 0; k < RPT; k++)
        idxs[k] = g_idx[row0 + k * 4 + lr];

    // batch the 4 independent gathers
    float4 v[RPT];
    #pragma unroll
    for (int k = 0; k < RPT; k++) {
        if (idxs[k] >= 0)
            v[k] = __ldg(&xb[(size_t)idxs[k] * D4_ + c]);
        else
            v[k] = make_float4(0.f, 0.f, 0.f, 0.f);
    }

    // stage into smem (STS: no LSU store-issue tax, no bank conflicts)
    #pragma unroll
    for (int k = 0; k < RPT; k++)
        tile[(k * 4 + lr) * D4_ + c] = v[k];

    __syncthreads();

    // one bulk async store for the whole contiguous 24KB tile
    if (threadIdx.x == 0) {
        asm volatile("fence.proxy.async.shared::cta;" ::: "memory");
        const void* gdst = (const void*)(out + (size_t)row0 * D4_);
        uint32_t saddr = (uint32_t)__cvta_generic_to_shared(tile);
        asm volatile(
            "cp.async.bulk.global.shared::cta.bulk_group [%0], [%1], %2;"
            :: "l"(gdst), "r"(saddr), "r"((int)TILE_BYTES) : "memory");
        asm volatile("cp.async.bulk.commit_group;" ::: "memory");
        asm volatile("cp.async.bulk.wait_group 0;" ::: "memory");
    }
}

extern "C" void kernel_launch(void* const* d_in, const int* in_sizes, int n_in,
                              void* d_out, int out_size) {
    const float* xs = (const float*)d_in[0];   // (16,1024,384) f32
    const int*   ds = (const int*)d_in[1];     // (16,1024) i32
    float* out = (float*)d_out;                // (16,4096,384) f32

    scan_idx_kernel<<<B_, T_>>>(ds);
    gather_kernel<<<(B_ * OUTLEN_) / ROWS_PER_CTA, G_THREADS>>>(
        (const float4*)xs, (float4*)out);
}